// round 14
// baseline (speedup 1.0000x reference)
#include <cuda_runtime.h>
#include <math.h>

#define BB   8
#define HH   256
#define WW   256
#define HW   (HH*WW)
#define RPB  2
#define NHB  (BB*HH/RPB)          // 1024 horizontal (consumer) blocks
#define NVB  128                  // 128 vertical (producer) blocks, bids 0..127

// Scratch (no device allocations allowed).
__device__ float2   g_dv[BB*HW];  // vertical EDT^2 per pixel (pos,neg); L2-resident
__device__ float    g_pp[NHB];
__device__ float    g_pw[NHB];
__device__ float    g_pc[NHB];
__device__ unsigned g_ticket;     // zero-init; last consumer resets to 0
__device__ unsigned g_vdone[BB];  // producers done per image; reset by last consumer

// ---------------------------------------------------------------------------
// One launch, two roles by blockIdx.x:
//   bids 0..127   : PRODUCERS — vertical EDT via per-column register bitmasks.
//                   (image b, stripe k of 32 cols, half of each 32-row group.)
//                   All producers sit in deterministic wave 1 (bids < 148).
//   bids 128..1151: CONSUMERS — spin on g_vdone[b]==16, then horizontal
//                   envelope + loss + reduction (proven R13 structure).
// ---------------------------------------------------------------------------
__global__ void __launch_bounds__(256) fused_kernel(
    const float* __restrict__ logits, const int* __restrict__ targets,
    float* __restrict__ out) {
    int bid = blockIdx.x;
    int tid = threadIdx.x;

    if (bid < NVB) {
        // ================= PRODUCER: vertical EDT =================
        int b    = bid >> 4;           // image
        int sub  = bid & 15;
        int k    = sub >> 1;           // 32-col stripe
        int half = sub & 1;            // pixels i in [16*half, 16*half+16)
        int g    = tid >> 5;           // row group 0..7
        int l    = tid & 31;
        int col  = (k << 5) + l;

        // build this group's column word (coalesced across lanes)
        const int* p = targets + b * HW + (g << 5) * WW + col;
        unsigned cw = 0;
#pragma unroll
        for (int j = 0; j < 32; j++) { cw |= ((unsigned)(*p)) << j; p += WW; }

        __shared__ unsigned scol[8][32];
        scol[g][l] = cw;
        __syncthreads();

        unsigned prev1 = (g > 0) ?  scol[g - 1][l] : 0u;
        unsigned next1 = (g < 7) ?  scol[g + 1][l] : 0u;
        unsigned cw0   = ~cw;
        unsigned prev0 = (g > 0) ? ~scol[g - 1][l] : 0u;  // border: no rows -> no 0s
        unsigned next0 = (g < 7) ? ~scol[g + 1][l] : 0u;

        // bit (32+j) of catA = row Rbase+j ; bit j = row Rbase-32+j
        unsigned long long catA1 = (unsigned long long)prev1 | ((unsigned long long)cw  << 32);
        unsigned long long catB1 = (unsigned long long)cw    | ((unsigned long long)next1 << 32);
        unsigned long long catA0 = (unsigned long long)prev0 | ((unsigned long long)cw0 << 32);
        unsigned long long catB0 = (unsigned long long)cw0   | ((unsigned long long)next0 << 32);

        int Rbase = g << 5;
        int i0    = half << 4;
        float2* outp = g_dv + b * HW + (Rbase + i0) * WW + col;

#pragma unroll 8
        for (int q = 0; q < 16; q++) {
            int i  = i0 + q;
            int me = (int)((cw >> i) & 1u);

            unsigned A1 = (unsigned)(catA1 >> i);
            unsigned B1 = (unsigned)(catB1 >> (i + 1));
            unsigned A0 = (unsigned)(catA0 >> i);
            unsigned B0 = (unsigned)(catB0 >> (i + 1));

            int r1, r0;
            if (me) r1 = 0;
            else {
                int da = A1 ? (__clz((int)A1) + 1) : 1000;
                int db = B1 ? __ffs((int)B1)       : 1000;
                r1 = min(da, db);
            }
            if (!me) r0 = 0;
            else {
                int da = A0 ? (__clz((int)A0) + 1) : 1000;
                int db = B0 ? __ffs((int)B0)       : 1000;
                r0 = min(da, db);
            }

            if (r1 >= 1000 || r0 >= 1000) {    // P~2^-32/px: exact serial tail
                int R = Rbase + i;
                const int* tc = targets + b * HW + col;
#pragma unroll 1
                for (int r = 33; r < HH; r++) {
                    if (r1 < 1000 && r0 < 1000) break;
                    int tu = tc[max(R - r, 0) * WW];
                    int td = tc[min(R + r, HH - 1) * WW];
                    if (r1 >= 1000 && (tu | td))      r1 = r;
                    if (r0 >= 1000 && (tu & td) == 0) r0 = r;
                }
            }

            float d2p = (r1 <= 255) ? (float)(r1 * r1) : 1e9f;
            float d2n = (r0 <= 255) ? (float)(r0 * r0) : 1e9f;
            *outp = make_float2(d2p, d2n);     // coalesced across lanes
            outp += WW;
        }

        __threadfence();                       // publish g_dv before the flag
        __syncthreads();
        if (tid == 0) atomicAdd(&g_vdone[b], 1u);
        return;
    }

    // ================= CONSUMER: horizontal envelope + loss =================
    int blk = bid - NVB;           // 0..1023
    int b   = blk >> 7;
    int h0  = (blk & 127) * RPB;
    int w   = tid;

    // wait until image b's vertical data is complete (producers are wave-1)
    if (w == 0) {
        while (atomicAdd(&g_vdone[b], 0u) < 16u) __nanosleep(64);
    }
    __syncthreads();

    // prologue: issue all gmem loads together
    float l0_[RPB], l1_[RPB];
    float2 v_[RPB];
#pragma unroll
    for (int i = 0; i < RPB; i++) {
        l0_[i] = logits[((b * 2 + 0) * HH + (h0 + i)) * WW + w];
        l1_[i] = logits[((b * 2 + 1) * HH + (h0 + i)) * WW + w];
        v_[i]  = g_dv[b * HW + (h0 + i) * WW + w];
    }

    __shared__ float2 srow[RPB][WW + 16];      // +-8 BIG pads
    if (w < 8) {
#pragma unroll
        for (int i = 0; i < RPB; i++) {
            srow[i][w]          = make_float2(1e9f, 1e9f);
            srow[i][WW + 8 + w] = make_float2(1e9f, 1e9f);
        }
    }
#pragma unroll
    for (int i = 0; i < RPB; i++) srow[i][8 + w] = v_[i];
    __syncthreads();

    float pred_[RPB];
#pragma unroll
    for (int i = 0; i < RPB; i++)
        pred_[i] = __fdividef(1.0f, 1.0f + __expf(l0_[i] - l1_[i]));

    float accP = 0.f, accW = 0.f;

#pragma unroll
    for (int i = 0; i < RPB; i++) {
        const float2* c = &srow[i][8 + w];
        float bp = v_[i].x, bn = v_[i].y;

        float2 L1 = c[-1], R1 = c[1];
        float2 L2 = c[-2], R2 = c[2];
        float2 L3 = c[-3], R3 = c[3];
        float2 L4 = c[-4], R4 = c[4];
        bp = fminf(bp, fminf(L1.x, R1.x) + 1.0f);  bn = fminf(bn, fminf(L1.y, R1.y) + 1.0f);
        bp = fminf(bp, fminf(L2.x, R2.x) + 4.0f);  bn = fminf(bn, fminf(L2.y, R2.y) + 4.0f);
        bp = fminf(bp, fminf(L3.x, R3.x) + 9.0f);  bn = fminf(bn, fminf(L3.y, R3.y) + 9.0f);
        bp = fminf(bp, fminf(L4.x, R4.x) + 16.0f); bn = fminf(bn, fminf(L4.y, R4.y) + 16.0f);

        if (fmaxf(bp, bn) > 25.0f) {
            float2 L5 = c[-5], R5 = c[5];
            float2 L6 = c[-6], R6 = c[6];
            float2 L7 = c[-7], R7 = c[7];
            float2 L8 = c[-8], R8 = c[8];
            bp = fminf(bp, fminf(L5.x, R5.x) + 25.0f); bn = fminf(bn, fminf(L5.y, R5.y) + 25.0f);
            bp = fminf(bp, fminf(L6.x, R6.x) + 36.0f); bn = fminf(bn, fminf(L6.y, R6.y) + 36.0f);
            bp = fminf(bp, fminf(L7.x, R7.x) + 49.0f); bn = fminf(bn, fminf(L7.y, R7.y) + 49.0f);
            bp = fminf(bp, fminf(L8.x, R8.x) + 64.0f); bn = fminf(bn, fminf(L8.y, R8.y) + 64.0f);

            if (fmaxf(bp, bn) > 81.0f) {       // rare exact serial tail
#pragma unroll 1
                for (int r = 9; r < WW; r++) {
                    float rr = (float)(r * r);
                    if (rr >= bp && rr >= bn) break;
                    if (w - r >= 0) {
                        float2 a = srow[i][8 + w - r];
                        bp = fminf(bp, a.x + rr); bn = fminf(bn, a.y + rr);
                    }
                    if (w + r < WW) {
                        float2 d = srow[i][8 + w + r];
                        bp = fminf(bp, d.x + rr); bn = fminf(bn, d.y + rr);
                    }
                }
            }
        }

        accP += pred_[i];
        accW += pred_[i] * (sqrtf(bp) - sqrtf(bn));
    }

    // ---- counts via ballots (gt <=> vertical d2p == 0) ----
    unsigned m = 0xFFFFFFFFu;
    int wcnt = 0;
#pragma unroll
    for (int i = 0; i < RPB; i++)
        wcnt += __popc(__ballot_sync(m, v_[i].x == 0.0f));
    float cv = (float)wcnt;

    // ---- deterministic block reduction ----
#pragma unroll
    for (int o = 16; o > 0; o >>= 1) {
        accP += __shfl_down_sync(m, accP, o);
        accW += __shfl_down_sync(m, accW, o);
    }
    __shared__ float rr0[8], rr1[8], rr2[8];
    if ((w & 31) == 0) {
        rr0[w >> 5] = accP; rr1[w >> 5] = accW; rr2[w >> 5] = cv;
    }
    __syncthreads();

    __shared__ bool s_last;
    if (w == 0) {
        float s0 = 0.f, s1 = 0.f, s2 = 0.f;
#pragma unroll
        for (int i = 0; i < 8; i++) { s0 += rr0[i]; s1 += rr1[i]; s2 += rr2[i]; }
        g_pp[blk] = s0;
        g_pw[blk] = s1;
        g_pc[blk] = s2;
        __threadfence();
        unsigned tk = atomicAdd(&g_ticket, 1u);
        s_last = (tk == (unsigned)(NHB - 1));
    }
    __syncthreads();
    if (!s_last) return;

    // ---- last consumer: global reduction (deterministic order) ----
    int wb   = w >> 5;
    int lane = w & 31;
    int base = wb * 128;
    float s0 = 0.f, s1 = 0.f, s2 = 0.f;
#pragma unroll
    for (int i = 0; i < 4; i++) {
        int idx = base + lane + i * 32;
        s0 += __ldcg(&g_pp[idx]);
        s1 += __ldcg(&g_pw[idx]);
        s2 += __ldcg(&g_pc[idx]);
    }
#pragma unroll
    for (int o = 16; o > 0; o >>= 1) {
        s0 += __shfl_down_sync(m, s0, o);
        s1 += __shfl_down_sync(m, s1, o);
        s2 += __shfl_down_sync(m, s2, o);
    }
    __shared__ float pb[8];
    if (lane == 0) {
        float inv = 1.0f / (float)HW;
        float mean_pred = s0 * inv;
        float mean_w    = s1 * inv;
        float per_b;
        if (s2 == 0.0f)           per_b = mean_pred;
        else if (s2 == (float)HW) per_b = 1.0f - mean_pred;
        else                      per_b = mean_w;
        pb[wb] = per_b;
    }
    __syncthreads();
    if (w == 0) {
        float total = 0.f;
#pragma unroll
        for (int i = 0; i < BB; i++) total += pb[i];
        out[0] = total / (float)BB;
        g_ticket = 0;                          // reset for next graph replay
#pragma unroll
        for (int i = 0; i < BB; i++) g_vdone[i] = 0u;
    }
}

extern "C" void kernel_launch(void* const* d_in, const int* in_sizes, int n_in,
                              void* d_out, int out_size) {
    const float* logits  = (const float*)d_in[0];
    const int*   targets = (const int*)d_in[1];
    float*       out     = (float*)d_out;

    fused_kernel<<<NVB + NHB, 256>>>(logits, targets, out);
}

// round 15
// speedup vs baseline: 1.3325x; 1.3325x over previous
#include <cuda_runtime.h>
#include <math.h>

#define BB   8
#define HH   256
#define WW   256
#define HW   (HH*WW)
#define RPB  4
#define NBLK (BB*HH/RPB)   // 512 blocks, 64 per image

// Scratch (no device allocations allowed): per-block partials + ticket.
__device__ float    g_pp[NBLK];
__device__ float    g_pw[NBLK];
__device__ float    g_pc[NBLK];
__device__ unsigned g_ticket;     // zero-init; last block resets to 0

// ---------------------------------------------------------------------------
// Fused kernel: one block per 4 rows (same image), one thread per column.
// Best-measured R8 skeleton + proven micro-opts:
//  - Prologue issues ALL gmem loads together (8 logits + 12 target rows).
//  - Interior blocks (62/64) skip border clamping.
//  - Vertical r=1..4 prefix masks from registers (exact; clamped bits only
//    re-assert facts from <= radii); serial exact gmem tail from r=5.
//  - Horizontal envelope: r<=2 unconditional (4 LDS.64), r=3..4 chunk only if
//    max(bp,bn)>4 (~2% of warp-rows), bounds-checked serial tail from r=5 if
//    max>25. Exact: candidate at radius r is >= r^2, so it can only improve a
//    best that exceeds r^2; min is order-independent; monotone rounding.
//  - Ballot counts; 2-var shuffle tree; single barrier; last-block global
//    reduction (threadfence + ticket; deterministic order).
// ---------------------------------------------------------------------------
__global__ void __launch_bounds__(256) fused_kernel(
    const float* __restrict__ logits, const int* __restrict__ targets,
    float* __restrict__ out) {
    int blk = blockIdx.x;          // 0..511
    int b   = blk >> 6;            // image
    int h0  = (blk & 63) * RPB;    // first of 4 rows
    int w   = threadIdx.x;

    const int* tcol = targets + b * HW + w;   // column w, stride WW

    // ---- prologue: issue ALL gmem loads together (20 outstanding LDGs) ----
    const float* Lp0 = logits + (b * 2 + 0) * HW + h0 * WW + w;
    const float* Lp1 = logits + (b * 2 + 1) * HW + h0 * WW + w;
    float l0_[RPB], l1_[RPB];
#pragma unroll
    for (int i = 0; i < RPB; i++) { l0_[i] = Lp0[i * WW]; l1_[i] = Lp1[i * WW]; }

    int t[RPB + 8];                // rows h0-4 .. h0+7
    if (h0 >= 4 && h0 + RPB + 3 < HH) {       // interior: no clamping
#pragma unroll
        for (int j = 0; j < RPB + 8; j++) t[j] = tcol[(h0 - 4 + j) * WW];
    } else {
#pragma unroll
        for (int j = 0; j < RPB + 8; j++) {
            int hh = min(max(h0 - 4 + j, 0), HH - 1);
            t[j] = tcol[hh * WW];
        }
    }

    __shared__ float2 srow[RPB][WW + 16];     // +-8 BIG pads
    if (w < 8) {
#pragma unroll
        for (int i = 0; i < RPB; i++) {
            srow[i][w]          = make_float2(1e9f, 1e9f);
            srow[i][WW + 8 + w] = make_float2(1e9f, 1e9f);
        }
    }

    float d2p_[RPB], d2n_[RPB];

#pragma unroll
    for (int i = 0; i < RPB; i++) {
        int hl = i + 4;
        int me = t[hl];
        unsigned m1 = 0, m0 = 0;
#pragma unroll
        for (int r = 1; r <= 4; r++) {
            int o = t[hl - r] | t[hl + r];
            int a = t[hl - r] & t[hl + r];
            m1 |= (unsigned)o << (r - 1);
            m0 |= (unsigned)(a ^ 1) << (r - 1);
        }
        int r1 = me        ? 0 : (m1 ? __ffs(m1) : 256);
        int r0 = (me == 0) ? 0 : (m0 ? __ffs(m0) : 256);

        if ((r1 | r0) >= 256) {               // rare exact gmem tail
            int h = h0 + i;
#pragma unroll 1
            for (int r = 5; r < HH; r++) {
                if ((r1 | r0) < 256) break;
                int tu = tcol[max(h - r, 0) * WW];
                int td = tcol[min(h + r, HH - 1) * WW];
                if (r1 == 256 && (tu | td))      r1 = r;
                if (r0 == 256 && (tu & td) == 0) r0 = r;
            }
        }
        d2p_[i] = (r1 <= 255) ? (float)(r1 * r1) : 1e9f;
        d2n_[i] = (r0 <= 255) ? (float)(r0 * r0) : 1e9f;
        srow[i][8 + w] = make_float2(d2p_[i], d2n_[i]);
    }
    __syncthreads();

    // sigmoid while other warps are in the barrier / LDS phase
    float pred_[RPB];
#pragma unroll
    for (int i = 0; i < RPB; i++)
        pred_[i] = __fdividef(1.0f, 1.0f + __expf(l0_[i] - l1_[i]));

    float accP = 0.f, accW = 0.f;

#pragma unroll
    for (int i = 0; i < RPB; i++) {
        const float2* c = &srow[i][8 + w];
        float bp = d2p_[i], bn = d2n_[i];

        // unconditional prefix r=1..2 (4 independent LDS.64, one wall)
        float2 L1 = c[-1], R1 = c[1];
        float2 L2 = c[-2], R2 = c[2];
        bp = fminf(bp, fminf(L1.x, R1.x) + 1.0f); bn = fminf(bn, fminf(L1.y, R1.y) + 1.0f);
        bp = fminf(bp, fminf(L2.x, R2.x) + 4.0f); bn = fminf(bn, fminf(L2.y, R2.y) + 4.0f);

        if (fmaxf(bp, bn) > 4.0f) {           // r>=3 can only help if best > 9? no: gate at 4 is
                                              // conservative-safe (enter whenever r=3 could matter)
            float2 L3 = c[-3], R3 = c[3];
            float2 L4 = c[-4], R4 = c[4];
            bp = fminf(bp, fminf(L3.x, R3.x) + 9.0f);  bn = fminf(bn, fminf(L3.y, R3.y) + 9.0f);
            bp = fminf(bp, fminf(L4.x, R4.x) + 16.0f); bn = fminf(bn, fminf(L4.y, R4.y) + 16.0f);

            if (fmaxf(bp, bn) > 25.0f) {      // rare exact serial tail
#pragma unroll 1
                for (int r = 5; r < WW; r++) {
                    float rr = (float)(r * r);
                    if (rr >= bp && rr >= bn) break;
                    if (w - r >= 0) {
                        float2 a = srow[i][8 + w - r];
                        bp = fminf(bp, a.x + rr); bn = fminf(bn, a.y + rr);
                    }
                    if (w + r < WW) {
                        float2 d = srow[i][8 + w + r];
                        bp = fminf(bp, d.x + rr); bn = fminf(bn, d.y + rr);
                    }
                }
            }
        }

        accP += pred_[i];
        accW += pred_[i] * (sqrtf(bp) - sqrtf(bn));
    }

    // ---- warp counts via ballots (warp-uniform) ----
    unsigned m = 0xFFFFFFFFu;
    int wcnt = 0;
#pragma unroll
    for (int i = 0; i < RPB; i++)
        wcnt += __popc(__ballot_sync(m, t[i + 4]));
    float cv = (float)wcnt;

    // ---- deterministic block reduction (2 shuffled vars, 1 barrier) ----
#pragma unroll
    for (int o = 16; o > 0; o >>= 1) {
        accP += __shfl_down_sync(m, accP, o);
        accW += __shfl_down_sync(m, accW, o);
    }
    __shared__ float rr0[8], rr1[8], rr2[8];
    if ((w & 31) == 0) {
        rr0[w >> 5] = accP; rr1[w >> 5] = accW; rr2[w >> 5] = cv;
    }
    __syncthreads();

    __shared__ bool s_last;
    if (w == 0) {
        float s0 = 0.f, s1 = 0.f, s2 = 0.f;
#pragma unroll
        for (int i = 0; i < 8; i++) { s0 += rr0[i]; s1 += rr1[i]; s2 += rr2[i]; }
        g_pp[blk] = s0;
        g_pw[blk] = s1;
        g_pc[blk] = s2;
        __threadfence();
        unsigned tk = atomicAdd(&g_ticket, 1u);
        s_last = (tk == (unsigned)(NBLK - 1));
    }
    __syncthreads();
    if (!s_last) return;

    // ---- last block: global reduction (deterministic order) ----
    int wb   = w >> 5;             // batch handled by this warp
    int lane = w & 31;
    int base = wb * 64;            // 64 partials per image
    float s0 = __ldcg(&g_pp[base + lane]) + __ldcg(&g_pp[base + 32 + lane]);
    float s1 = __ldcg(&g_pw[base + lane]) + __ldcg(&g_pw[base + 32 + lane]);
    float s2 = __ldcg(&g_pc[base + lane]) + __ldcg(&g_pc[base + 32 + lane]);
#pragma unroll
    for (int o = 16; o > 0; o >>= 1) {
        s0 += __shfl_down_sync(m, s0, o);
        s1 += __shfl_down_sync(m, s1, o);
        s2 += __shfl_down_sync(m, s2, o);
    }
    __shared__ float pb[8];
    if (lane == 0) {
        float inv = 1.0f / (float)HW;
        float mean_pred = s0 * inv;
        float mean_w    = s1 * inv;
        float per_b;
        if (s2 == 0.0f)           per_b = mean_pred;
        else if (s2 == (float)HW) per_b = 1.0f - mean_pred;
        else                      per_b = mean_w;
        pb[wb] = per_b;
    }
    __syncthreads();
    if (w == 0) {
        float total = 0.f;
#pragma unroll
        for (int i = 0; i < BB; i++) total += pb[i];
        out[0] = total / (float)BB;
        g_ticket = 0;                          // reset for next graph replay
    }
}

extern "C" void kernel_launch(void* const* d_in, const int* in_sizes, int n_in,
                              void* d_out, int out_size) {
    const float* logits  = (const float*)d_in[0];
    const int*   targets = (const int*)d_in[1];
    float*       out     = (float*)d_out;

    fused_kernel<<<NBLK, 256>>>(logits, targets, out);
}